// round 10
// baseline (speedup 1.0000x reference)
#include <cuda_runtime.h>

#define N_BINS 85
#define NBLOCKS 1184            // 8 CTAs/SM * 148 SMs (empirical best shape)
#define GROUPS_PER_BLOCK 3
#define ACTIVE_THREADS (GROUPS_PER_BLOCK * N_BINS)   // 255
#define BLOCK_THREADS 256
#define TOTAL_GROUPS (NBLOCKS * GROUPS_PER_BLOCK)    // 3552

// Globals (zero at module load; last block resets via atomicExch each call,
// so graph replays are deterministic). No dynamic allocation.
__device__ float g_acc[N_BINS];
__device__ unsigned int g_count;

// ---------------------------------------------------------------------------
// DRAM-locality version:
//  * each group owns a CONTIGUOUS slice of super-rows (sequential addresses,
//    good HBM row-buffer locality), not a 4.8MB-stride grid-stride walk;
//  * the two input streams are PHASE-SPLIT: loop 1 streams `in` (+), loop 2
//    streams `tg` (-), so a warp never ping-pongs rows between two arrays.
// Per-thread partial still ends as S_in - S_tg of its slice -> same
// cancellation-friendly numerics as before.
// Epilogue: one fence per block + ticket; last block finishes (cheap, proven).
// ---------------------------------------------------------------------------
__global__ void __launch_bounds__(BLOCK_THREADS, 8)
emd_fused(const float4* __restrict__ in4, const float4* __restrict__ tg4,
          const float* __restrict__ in, const float* __restrict__ tg,
          int nsuper, int slice_len, int total_elems, float* __restrict__ out)
{
    __shared__ float sd[N_BINS];
    __shared__ int islast;
    int t = threadIdx.x;
    if (t < N_BINS) sd[t] = 0.0f;

    float a0 = 0.f, a1 = 0.f, a2 = 0.f, a3 = 0.f;
    int p = 0;
    if (t < ACTIVE_THREADS) {
        int g = blockIdx.x * GROUPS_PER_BLOCK + (t / N_BINS);
        p = t % N_BINS;
        int s0 = g * slice_len;
        int s1 = s0 + slice_len;
        if (s1 > nsuper) s1 = nsuper;

        // Phase 1: stream `in` contiguously (+)
        #pragma unroll 4
        for (int s = s0; s < s1; s++) {
            int idx = s * N_BINS + p;          // float4 index
            float4 a = in4[idx];
            a0 += a.x; a1 += a.y; a2 += a.z; a3 += a.w;
        }
        // Phase 2: stream `tg` contiguously (-)
        #pragma unroll 4
        for (int s = s0; s < s1; s++) {
            int idx = s * N_BINS + p;
            float4 b = tg4[idx];
            a0 -= b.x; a1 -= b.y; a2 -= b.z; a3 -= b.w;
        }
    }
    __syncthreads();
    if (t < ACTIVE_THREADS) {
        atomicAdd(&sd[(4 * p) % N_BINS],     a0);
        atomicAdd(&sd[(4 * p + 1) % N_BINS], a1);
        atomicAdd(&sd[(4 * p + 2) % N_BINS], a2);
        atomicAdd(&sd[(4 * p + 3) % N_BINS], a3);
    }
    // Tail rows (B % 4 != 0): scalar, block 0 only. (B=500000 -> empty loop.)
    if (blockIdx.x == 0) {
        int tail_start = nsuper * (4 * N_BINS);
        for (int i = tail_start + t; i < total_elems; i += BLOCK_THREADS) {
            atomicAdd(&sd[i % N_BINS], in[i] - tg[i]);
        }
    }
    __syncthreads();

    // Publish block partials via L2 float atomics (85 distinct addresses).
    if (t < N_BINS) atomicAdd(&g_acc[t], sd[t]);
    __syncthreads();          // publishers' atomics visible to t0 (block scope)
    if (t == 0) {
        __threadfence();      // ONE cumulative release fence per block
        unsigned int ticket = atomicAdd(&g_count, 1u);
        islast = (ticket == NBLOCKS - 1u);
    }
    __syncthreads();

    if (islast) {
        __shared__ float d[N_BINS];
        if (t == 0) __threadfence();           // acquire side
        __syncthreads();
        if (t < N_BINS) {
            // L2-coherent read + reset in one atomic; no L1 staleness possible.
            float v = atomicExch(&g_acc[t], 0.0f);
            d[t] = fabsf(v);
        }
        __syncthreads();
        if (t == 0) {
            float cum = 0.f, loss = 0.f;
            #pragma unroll
            for (int j = 0; j < N_BINS; j++) {
                cum += d[j];
                loss += cum / (float)(j + 1);
            }
            out[0] = loss * 0.1f;
            atomicExch(&g_count, 0u);          // reset ticket for next replay
        }
    }
}

extern "C" void kernel_launch(void* const* d_in, const int* in_sizes, int n_in,
                              void* d_out, int out_size)
{
    const float* in = (const float*)d_in[0];
    const float* tg = (const float*)d_in[1];
    int total = in_sizes[0];            // 500000 * 85
    int B = total / N_BINS;
    int nsuper = B / 4;                 // 125000
    int slice_len = (nsuper + TOTAL_GROUPS - 1) / TOTAL_GROUPS;   // 36

    emd_fused<<<NBLOCKS, BLOCK_THREADS>>>((const float4*)in, (const float4*)tg,
                                          in, tg, nsuper, slice_len, total,
                                          (float*)d_out);
}